// round 16
// baseline (speedup 1.0000x reference)
#include <cuda_runtime.h>
#include <cstdint>

#define N_TOTAL 10000
#define NPAD 10112         // NTILES*128, padded row count
#define D 128
#define BSZ 100
#define FEAT 3072
#define TOPK 50
#define NTILES 79
#define TRI_BLOCKS (NTILES * (NTILES + 1) / 2)
#define CAP 2048
#define NF4 2500

#define KC 32
#define SLD 36
#define SC_SMEM (4 * 128 * SLD * 4)   // 73728 B dynamic smem (scores)

// ---------------- scratch (device globals) ---------------------------------
__device__ float g_x[(size_t)N_TOTAL * D];
__device__ float g_y[(size_t)N_TOTAL * D];                 // -2 * out * sw
__device__ float g_a[N_TOTAL];
__device__ float g_scores[(size_t)N_TOTAL * N_TOTAL];      // 400 MB scratch
// pre-split tf32 operands (zero-padded rows up to NPAD)
__device__ unsigned g_yh[(size_t)NPAD * D];
__device__ unsigned g_yl[(size_t)NPAD * D];
__device__ unsigned g_oh[(size_t)NPAD * D];
__device__ unsigned g_ol[(size_t)NPAD * D];
__device__ unsigned g_wh[(size_t)D * FEAT];
__device__ unsigned g_wl[(size_t)D * FEAT];

// ---------------- tf32 / mma helpers ----------------------------------------
__device__ __forceinline__ unsigned tf32_of(float x) {
    unsigned r;
    asm("cvt.rna.tf32.f32 %0, %1;" : "=r"(r) : "f"(x));
    return r;
}
__device__ __forceinline__ void mma_tf32(float* c, const unsigned* a,
                                         const unsigned* b) {
    asm volatile(
        "mma.sync.aligned.m16n8k8.row.col.f32.tf32.tf32.f32 "
        "{%0,%1,%2,%3}, {%4,%5,%6,%7}, {%8,%9}, {%0,%1,%2,%3};"
        : "+f"(c[0]), "+f"(c[1]), "+f"(c[2]), "+f"(c[3])
        : "r"(a[0]), "r"(a[1]), "r"(a[2]), "r"(a[3]), "r"(b[0]), "r"(b[1]));
}

// ===========================================================================
// Prep A: split W1 into tf32 hi/lo (before gemm1)
// ===========================================================================
__global__ void prep_w_kernel(const float* __restrict__ W) {
    for (int i = blockIdx.x * blockDim.x + threadIdx.x; i < D * FEAT;
         i += gridDim.x * blockDim.x) {
        float w = W[i];
        unsigned h = tf32_of(w);
        g_wh[i] = h;
        g_wl[i] = tf32_of(w - __uint_as_float(h));
    }
}

// ===========================================================================
// Prep B: split g_y and outputs into tf32 hi/lo, rows >= N_TOTAL zeroed.
// ===========================================================================
__global__ void prep_yo_kernel(const float* __restrict__ O) {
    for (int i = blockIdx.x * blockDim.x + threadIdx.x; i < NPAD * D;
         i += gridDim.x * blockDim.x) {
        int row = i >> 7;
        float yv = 0.f, ov = 0.f;
        if (row < N_TOTAL) {
            yv = g_y[i];
            ov = O[i];
        }
        unsigned yh = tf32_of(yv);
        g_yh[i] = yh;
        g_yl[i] = tf32_of(yv - __uint_as_float(yh));
        unsigned oh = tf32_of(ov);
        g_oh[i] = oh;
        g_ol[i] = tf32_of(ov - __uint_as_float(oh));
    }
}

// ===========================================================================
// Kernel 1: x = inputs @ W1^T + b1 via 3xTF32 mma.sync.
// Tile 32(M) x 128(N=full), 256 threads = 8 warps as 2(M) x 4(N);
// per warp 16x32 = 1 m-tile x 4 n-tiles. K in 96 chunks of 32.
// A split in-kernel (each row owned by one block); W pre-split.
// ===========================================================================
__global__ void __launch_bounds__(256, 2)
gemm1_kernel(const float* __restrict__ A, const float* __restrict__ b1) {
    __shared__ __align__(16) unsigned Ah[32][SLD];
    __shared__ __align__(16) unsigned Al[32][SLD];
    __shared__ __align__(16) unsigned Bh[128][SLD];
    __shared__ __align__(16) unsigned Bl[128][SLD];

    const int tid = threadIdx.x;
    const int lane = tid & 31;
    const int wid = tid >> 5;
    const int warp_m = wid & 1;
    const int warp_n = wid >> 1;
    const int g = lane >> 2;
    const int tig = lane & 3;
    const int mbase = blockIdx.x * 32;

    float acc[4][4];
#pragma unroll
    for (int nt = 0; nt < 4; ++nt)
#pragma unroll
        for (int r = 0; r < 4; ++r) acc[nt][r] = 0.f;

    const int ar = tid >> 3;          // 0..31
    const int akk = (tid & 7) * 4;    // 0..28
    const int br = tid >> 1;          // 0..127
    const int bk = (tid & 1) * 16;    // 0 or 16

    for (int kc = 0; kc < FEAT; kc += KC) {
        // A: 32 rows x 32 k, split in-kernel
        {
            int m = mbase + ar;
            float4 v = make_float4(0.f, 0.f, 0.f, 0.f);
            if (m < N_TOTAL)
                v = *(const float4*)&A[(size_t)m * FEAT + kc + akk];
            const float e[4] = {v.x, v.y, v.z, v.w};
#pragma unroll
            for (int q = 0; q < 4; ++q) {
                unsigned h = tf32_of(e[q]);
                Ah[ar][akk + q] = h;
                Al[ar][akk + q] = tf32_of(e[q] - __uint_as_float(h));
            }
        }
        // B: 128 n-rows x 32 k, pure copy from pre-split W
#pragma unroll
        for (int q = 0; q < 4; ++q) {
            *(uint4*)&Bh[br][bk + 4 * q] =
                *(const uint4*)&g_wh[(size_t)br * FEAT + kc + bk + 4 * q];
            *(uint4*)&Bl[br][bk + 4 * q] =
                *(const uint4*)&g_wl[(size_t)br * FEAT + kc + bk + 4 * q];
        }
        __syncthreads();

#pragma unroll
        for (int ks = 0; ks < 4; ++ks) {
            const int k0 = ks * 8;
            const int m = warp_m * 16;
            unsigned ah[4], al[4];
            ah[0] = Ah[m + g][k0 + tig];
            ah[1] = Ah[m + g + 8][k0 + tig];
            ah[2] = Ah[m + g][k0 + tig + 4];
            ah[3] = Ah[m + g + 8][k0 + tig + 4];
            al[0] = Al[m + g][k0 + tig];
            al[1] = Al[m + g + 8][k0 + tig];
            al[2] = Al[m + g][k0 + tig + 4];
            al[3] = Al[m + g + 8][k0 + tig + 4];
#pragma unroll
            for (int nt = 0; nt < 4; ++nt) {
                int n = warp_n * 32 + nt * 8 + g;
                unsigned bh[2], bl[2];
                bh[0] = Bh[n][k0 + tig];
                bh[1] = Bh[n][k0 + tig + 4];
                bl[0] = Bl[n][k0 + tig];
                bl[1] = Bl[n][k0 + tig + 4];
                mma_tf32(acc[nt], ah, bh);
                mma_tf32(acc[nt], ah, bl);
                mma_tf32(acc[nt], al, bh);
            }
        }
        __syncthreads();
    }

    // epilogue: add bias, store
    const int gi0 = mbase + warp_m * 16 + g;
    const int gi1 = gi0 + 8;
#pragma unroll
    for (int nt = 0; nt < 4; ++nt) {
        int col = warp_n * 32 + nt * 8 + 2 * tig;
        float b0 = b1[col], bb1 = b1[col + 1];
        if (gi0 < N_TOTAL)
            *(float2*)&g_x[(size_t)gi0 * D + col] =
                make_float2(acc[nt][0] + b0, acc[nt][1] + bb1);
        if (gi1 < N_TOTAL)
            *(float2*)&g_x[(size_t)gi1 * D + col] =
                make_float2(acc[nt][2] + b0, acc[nt][3] + bb1);
    }
}

// ===========================================================================
// Kernel 2: BatchNorm per 100-row micro-batch + fused y/a
// ===========================================================================
__global__ void bn_kernel(const float* __restrict__ gamma,
                          const float* __restrict__ beta,
                          const float* __restrict__ sw,
                          float* __restrict__ outp) {
    const int b = blockIdx.x;
    const int c = threadIdx.x;
    __shared__ float arow[BSZ];
    if (c < BSZ) arow[c] = 0.f;

    const float* xb = g_x + (size_t)b * BSZ * D + c;
    float s = 0.f, s2 = 0.f;
    for (int r = 0; r < BSZ; ++r) {
        float v = xb[(size_t)r * D];
        s += v;
        s2 += v * v;
    }
    float mean = s * (1.f / BSZ);
    float var = s2 * (1.f / BSZ) - mean * mean;
    float rs = rsqrtf(var + 1e-5f);
    float g = gamma[c], be = beta[c], w = sw[c];
    __syncthreads();

    const int lane = c & 31;
    for (int r = 0; r < BSZ; ++r) {
        float v = xb[(size_t)r * D];
        float o = (v - mean) * rs * g + be;
        size_t idx = (size_t)(b * BSZ + r) * D + c;
        outp[idx] = o;
        g_y[idx] = -2.f * o * w;
        float contrib = w * o * o;
#pragma unroll
        for (int off = 16; off; off >>= 1)
            contrib += __shfl_down_sync(0xffffffffu, contrib, off);
        if (lane == 0) atomicAdd(&arow[r], contrib);
    }
    __syncthreads();
    if (c < BSZ) g_a[b * BSZ + c] = arow[c];
}

// ===========================================================================
// Kernel 3: scores via 3xTF32 mma.sync (R15 WIN structure); operand fill is
// now a pure uint4 copy from pre-split global arrays (no CVT, no guards).
// ===========================================================================
__global__ void __launch_bounds__(256, 2)
scores_kernel(const float* __restrict__ sbp) {
    extern __shared__ __align__(16) unsigned smem_u[];
    unsigned (*Ah)[SLD] = (unsigned(*)[SLD])smem_u;
    unsigned (*Al)[SLD] = (unsigned(*)[SLD])(smem_u + 128 * SLD);
    unsigned (*Bh)[SLD] = (unsigned(*)[SLD])(smem_u + 2 * 128 * SLD);
    unsigned (*Bl)[SLD] = (unsigned(*)[SLD])(smem_u + 3 * 128 * SLD);

    int tt = blockIdx.x;
    int bi = 0;
    while (tt >= NTILES - bi) { tt -= NTILES - bi; ++bi; }
    const int bj = bi + tt;

    const int tid = threadIdx.x;
    const int lane = tid & 31;
    const int wid = tid >> 5;
    const int warp_m = wid & 1;
    const int warp_n = wid >> 1;
    const int g = lane >> 2;
    const int tig = lane & 3;

    const int ibase = bi * 128;
    const int jbase = bj * 128;

    float acc[4][4][4];
#pragma unroll
    for (int mt = 0; mt < 4; ++mt)
#pragma unroll
        for (int nt = 0; nt < 4; ++nt)
#pragma unroll
            for (int r = 0; r < 4; ++r) acc[mt][nt][r] = 0.f;

    const int frow = tid >> 1;
    const int fc0 = (tid & 1) * 16;

    for (int kc = 0; kc < D; kc += KC) {
        // pure copies (rows padded in prep -> no bounds checks)
        {
            const size_t abase = (size_t)(ibase + frow) * D + kc + fc0;
            const size_t bbase = (size_t)(jbase + frow) * D + kc + fc0;
#pragma unroll
            for (int q = 0; q < 4; ++q) {
                *(uint4*)&Ah[frow][fc0 + 4 * q] = *(const uint4*)&g_yh[abase + 4 * q];
                *(uint4*)&Al[frow][fc0 + 4 * q] = *(const uint4*)&g_yl[abase + 4 * q];
                *(uint4*)&Bh[frow][fc0 + 4 * q] = *(const uint4*)&g_oh[bbase + 4 * q];
                *(uint4*)&Bl[frow][fc0 + 4 * q] = *(const uint4*)&g_ol[bbase + 4 * q];
            }
        }
        __syncthreads();

#pragma unroll
        for (int ks = 0; ks < 4; ++ks) {
            const int k0 = ks * 8;
            unsigned bh[4][2], bl[4][2];
#pragma unroll
            for (int nt = 0; nt < 4; ++nt) {
                int n = warp_n * 32 + nt * 8 + g;
                bh[nt][0] = Bh[n][k0 + tig];
                bh[nt][1] = Bh[n][k0 + tig + 4];
                bl[nt][0] = Bl[n][k0 + tig];
                bl[nt][1] = Bl[n][k0 + tig + 4];
            }
#pragma unroll
            for (int mt = 0; mt < 4; ++mt) {
                int m = warp_m * 64 + mt * 16;
                unsigned ah[4], al[4];
                ah[0] = Ah[m + g][k0 + tig];
                ah[1] = Ah[m + g + 8][k0 + tig];
                ah[2] = Ah[m + g][k0 + tig + 4];
                ah[3] = Ah[m + g + 8][k0 + tig + 4];
                al[0] = Al[m + g][k0 + tig];
                al[1] = Al[m + g + 8][k0 + tig];
                al[2] = Al[m + g][k0 + tig + 4];
                al[3] = Al[m + g + 8][k0 + tig + 4];
#pragma unroll
                for (int nt = 0; nt < 4; ++nt) {
                    mma_tf32(acc[mt][nt], ah, bh[nt]);
                    mma_tf32(acc[mt][nt], ah, bl[nt]);
                    mma_tf32(acc[mt][nt], al, bh[nt]);
                }
            }
        }
        __syncthreads();
    }

    // ---- epilogue: relu(a_i + a_j + sb + dot), store + mirror ----
    const float sbv = *sbp;
    const bool full = (ibase + 128 <= N_TOTAL) && (jbase + 128 <= N_TOTAL);

#pragma unroll
    for (int mt = 0; mt < 4; ++mt) {
        int gi0 = ibase + warp_m * 64 + mt * 16 + g;
        int gi1 = gi0 + 8;
        float ai0 = (gi0 < N_TOTAL) ? g_a[gi0] : 0.f;
        float ai1 = (gi1 < N_TOTAL) ? g_a[gi1] : 0.f;
#pragma unroll
        for (int nt = 0; nt < 4; ++nt) {
            int gj = jbase + warp_n * 32 + nt * 8 + 2 * tig;
            float aj0 = (gj < N_TOTAL) ? g_a[gj] : 0.f;
            float aj1 = (gj + 1 < N_TOTAL) ? g_a[gj + 1] : 0.f;
            const float* c = acc[mt][nt];
            float s00 = fmaxf(ai0 + aj0 + sbv + c[0], 0.f);
            float s01 = fmaxf(ai0 + aj1 + sbv + c[1], 0.f);
            float s10 = fmaxf(ai1 + aj0 + sbv + c[2], 0.f);
            float s11 = fmaxf(ai1 + aj1 + sbv + c[3], 0.f);
            if (full) {
                *(float2*)&g_scores[(size_t)gi0 * N_TOTAL + gj] =
                    make_float2(s00, s01);
                *(float2*)&g_scores[(size_t)gi1 * N_TOTAL + gj] =
                    make_float2(s10, s11);
                if (bi != bj) {
                    g_scores[(size_t)gj * N_TOTAL + gi0] = s00;
                    g_scores[(size_t)gj * N_TOTAL + gi1] = s10;
                    g_scores[(size_t)(gj + 1) * N_TOTAL + gi0] = s01;
                    g_scores[(size_t)(gj + 1) * N_TOTAL + gi1] = s11;
                }
            } else {
                if (gi0 < N_TOTAL && gj < N_TOTAL)
                    g_scores[(size_t)gi0 * N_TOTAL + gj] = s00;
                if (gi0 < N_TOTAL && gj + 1 < N_TOTAL)
                    g_scores[(size_t)gi0 * N_TOTAL + gj + 1] = s01;
                if (gi1 < N_TOTAL && gj < N_TOTAL)
                    g_scores[(size_t)gi1 * N_TOTAL + gj] = s10;
                if (gi1 < N_TOTAL && gj + 1 < N_TOTAL)
                    g_scores[(size_t)gi1 * N_TOTAL + gj + 1] = s11;
                if (bi != bj) {
                    if (gj < N_TOTAL && gi0 < N_TOTAL)
                        g_scores[(size_t)gj * N_TOTAL + gi0] = s00;
                    if (gj < N_TOTAL && gi1 < N_TOTAL)
                        g_scores[(size_t)gj * N_TOTAL + gi1] = s10;
                    if (gj + 1 < N_TOTAL && gi0 < N_TOTAL)
                        g_scores[(size_t)(gj + 1) * N_TOTAL + gi0] = s01;
                    if (gj + 1 < N_TOTAL && gi1 < N_TOTAL)
                        g_scores[(size_t)(gj + 1) * N_TOTAL + gi1] = s11;
                }
            }
        }
    }
}

// ===========================================================================
// Kernel 4: per-row exact top-50 — single-pass threshold buffer (R6 proven).
// ===========================================================================
__global__ void __launch_bounds__(256) topk_kernel(float* __restrict__ S) {
    __shared__ float bval[CAP];
    __shared__ int   bidx[CAP];
    __shared__ unsigned hist[256];
    __shared__ int idxbuf[64];
    __shared__ int eqbuf[256];
    __shared__ float vbuf[TOPK];
    __shared__ float ebuf[TOPK];
    __shared__ int bcount, cnt_gt, cnt_eq;
    __shared__ unsigned sh_sel;
    __shared__ int sh_krem, sh_binc;
    __shared__ unsigned sh_thr;
    __shared__ float sh_inv;

    const int row = blockIdx.x;
    const int tid = threadIdx.x;
    const int lane = tid & 31;

    const float* rowp = g_scores + (size_t)row * N_TOTAL;
    const float4* rp4 = (const float4*)rowp;
    float4* sp4 = (float4*)(S + (size_t)row * N_TOTAL);

    if (tid == 0) { bcount = 0; cnt_gt = 0; cnt_eq = 0; sh_thr = 0; }
    __syncthreads();

#define WARP_SELECT(ARR, KREM)                                                \
    if (tid < 32) {                                                           \
        unsigned h[8], ls[8];                                                 \
        int b0 = lane * 8;                                                    \
        _Pragma("unroll")                                                     \
        for (int j = 0; j < 8; ++j) h[j] = (ARR)[b0 + j];                     \
        ls[7] = h[7];                                                         \
        _Pragma("unroll")                                                     \
        for (int j = 6; j >= 0; --j) ls[j] = ls[j + 1] + h[j];                \
        unsigned tot = ls[0];                                                 \
        unsigned ss = tot;                                                    \
        _Pragma("unroll")                                                     \
        for (int off = 1; off < 32; off <<= 1) {                              \
            unsigned o = __shfl_down_sync(0xffffffffu, ss, off);              \
            if (lane + off < 32) ss += o;                                     \
        }                                                                     \
        unsigned above = ss - tot;                                            \
        int best = -1;                                                        \
        _Pragma("unroll")                                                     \
        for (int j = 7; j >= 0; --j)                                          \
            if (best < 0 && above + ls[j] >= (unsigned)(KREM)) best = j;      \
        unsigned m = __ballot_sync(0xffffffffu, best >= 0);                   \
        int hi = 31 - __clz((int)m);                                          \
        if (lane == hi) {                                                     \
            unsigned Sb = above + ls[best];                                   \
            sh_sel = (unsigned)(b0 + best);                                   \
            sh_binc = (int)h[best];                                           \
            sh_krem = (KREM) - (int)(Sb - h[best]);                           \
        }                                                                     \
    }

#define EXACT_SELECT(CNT, KINIT, PREFIX, KREM)                                \
    {                                                                         \
        (PREFIX) = 0; (KREM) = (KINIT);                                       \
        const int SHS[4] = {24, 16, 8, 0};                                    \
        const unsigned HMS[4] = {0u, 0xFF000000u, 0xFFFF0000u, 0xFFFFFF00u};  \
        for (int ps = 0; ps < 4; ++ps) {                                      \
            hist[tid] = 0;                                                    \
            __syncthreads();                                                  \
            for (int i = tid; i < (CNT); i += 256) {                          \
                unsigned b = __float_as_uint(bval[i]);                        \
                if ((b & HMS[ps]) == ((PREFIX) & HMS[ps]))                    \
                    atomicAdd(&hist[(b >> SHS[ps]) & 255u], 1u);              \
            }                                                                 \
            __syncthreads();                                                  \
            WARP_SELECT(hist, (KREM))                                         \
            __syncthreads();                                                  \
            (PREFIX) |= sh_sel << SHS[ps];                                    \
            (KREM) = sh_krem;                                                 \
            __syncthreads();                                                  \
        }                                                                     \
    }

#define PUSH(V, IDX)                                                          \
    {                                                                         \
        unsigned b_ = __float_as_uint(V);                                     \
        if (b_ >= thr) {                                                      \
            unsigned mk = __activemask();                                     \
            int ldr = __ffs(mk) - 1;                                          \
            int rk = __popc(mk & ((1u << lane) - 1));                         \
            int bs;                                                           \
            if (lane == ldr) bs = atomicAdd(&bcount, __popc(mk));             \
            bs = __shfl_sync(mk, bs, ldr);                                    \
            int p_ = bs + rk;                                                 \
            if (p_ < CAP) { bval[p_] = (V); bidx[p_] = (IDX); }               \
        }                                                                     \
    }

    unsigned thr = 0;
    const float4 z = make_float4(0.f, 0.f, 0.f, 0.f);

    for (int chunk = 0; chunk < 10; ++chunk) {
        if (bcount > CAP - 1024) {
            unsigned pfx; int kr;
            EXACT_SELECT(bcount, TOPK, pfx, kr)
            (void)kr;
            const int cnt = bcount;
            float mv[8]; int mi[8]; int mc = 0;
            for (int i = tid; i < cnt; i += 256) {
                unsigned b = __float_as_uint(bval[i]);
                if (b >= pfx) { mv[mc] = bval[i]; mi[mc] = bidx[i]; ++mc; }
            }
            __syncthreads();
            if (tid == 0) { bcount = 0; sh_thr = pfx; }
            __syncthreads();
            for (int j = 0; j < mc; ++j) {
                int p = atomicAdd(&bcount, 1);
                bval[p] = mv[j]; bidx[p] = mi[j];
            }
            __syncthreads();
            thr = sh_thr;
        }

        int i4 = chunk * 256 + tid;
        if (i4 < NF4) {
            float4 val = rp4[i4];
            sp4[i4] = z;
            PUSH(val.x, 4 * i4 + 0)
            PUSH(val.y, 4 * i4 + 1)
            PUSH(val.z, 4 * i4 + 2)
            PUSH(val.w, 4 * i4 + 3)
        }
        __syncthreads();
    }

    const int nc = bcount;
    unsigned prefix; int krem;
    EXACT_SELECT(nc, TOPK, prefix, krem)

    for (int i = tid; i < nc; i += 256) {
        unsigned b = __float_as_uint(bval[i]);
        if (b > prefix) {
            int p = atomicAdd(&cnt_gt, 1);
            idxbuf[p] = bidx[i];
        } else if (b == prefix) {
            int p = atomicAdd(&cnt_eq, 1);
            if (p < 256) eqbuf[p] = bidx[i];
        }
    }
    __syncthreads();

    if (tid == 0) {
        int n = cnt_gt;
        int need = TOPK - n;
        if (cnt_eq <= 256) {
            for (int t2 = 0; t2 < need; ++t2) {
                int best = 0x7fffffff, bj2 = 0;
                for (int j2 = 0; j2 < cnt_eq; ++j2) {
                    int vv = eqbuf[j2];
                    if (vv < best) { best = vv; bj2 = j2; }
                }
                idxbuf[n++] = best;
                eqbuf[bj2] = 0x7fffffff;
            }
        } else {
            for (int t2 = 0; t2 < need; ++t2) {
                int best = 0x7fffffff, bj2 = -1;
                for (int i = 0; i < nc; ++i) {
                    if (__float_as_uint(bval[i]) == prefix && bidx[i] < best) {
                        best = bidx[i]; bj2 = i;
                    }
                }
                idxbuf[n++] = best;
                if (bj2 >= 0) bidx[bj2] = 0x7fffffff;
            }
        }
    }
    __syncthreads();

    if (tid < TOPK) vbuf[tid] = rowp[idxbuf[tid]];
    __syncthreads();
    if (tid == 0) {
        float mx = -1e30f;
        for (int t2 = 0; t2 < TOPK; ++t2) mx = fmaxf(mx, vbuf[t2]);
        float ssum = 0.f;
        for (int t2 = 0; t2 < TOPK; ++t2) {
            float e = expf(vbuf[t2] - mx);
            ebuf[t2] = e;
            ssum += e;
        }
        sh_inv = 1.f / ssum;
    }
    __syncthreads();
    if (tid < TOPK)
        S[(size_t)row * N_TOTAL + idxbuf[tid]] = ebuf[tid] * sh_inv;

#undef PUSH
#undef EXACT_SELECT
#undef WARP_SELECT
}

// ===========================================================================
extern "C" void kernel_launch(void* const* d_in, const int* in_sizes, int n_in,
                              void* d_out, int out_size) {
    const float* inputs = (const float*)d_in[0];
    const float* W1     = (const float*)d_in[1];
    const float* b1     = (const float*)d_in[2];
    const float* gamma  = (const float*)d_in[3];
    const float* beta   = (const float*)d_in[4];
    const float* sw     = (const float*)d_in[5];
    const float* sb     = (const float*)d_in[6];

    float* outp = (float*)d_out;                       // [10000,128] outputs
    float* Sp   = outp + (size_t)N_TOTAL * D;          // [10000,10000] S

    cudaFuncSetAttribute(scores_kernel,
                         cudaFuncAttributeMaxDynamicSharedMemorySize, SC_SMEM);

    prep_w_kernel<<<296, 256>>>(W1);
    gemm1_kernel<<<(N_TOTAL + 31) / 32, 256>>>(inputs, b1);
    bn_kernel<<<N_TOTAL / BSZ, D>>>(gamma, beta, sw, outp);
    prep_yo_kernel<<<640, 256>>>(outp);
    scores_kernel<<<TRI_BLOCKS, 256, SC_SMEM>>>(sb);
    topk_kernel<<<N_TOTAL, 256>>>(Sp);
}

// round 17
// speedup vs baseline: 1.0512x; 1.0512x over previous
#include <cuda_runtime.h>
#include <cstdint>

#define N_TOTAL 10000
#define NPAD 10112         // NTILES*128, padded row count
#define D 128
#define BSZ 100
#define FEAT 3072
#define TOPK 50
#define NTILES 79
#define TRI_BLOCKS (NTILES * (NTILES + 1) / 2)
#define CAP 2048
#define NF4 2500

#define KC 32
#define SLD 36
#define SC_SMEM (4 * 128 * SLD * 4)   // 73728 B dynamic smem (scores)

// ---------------- scratch (device globals) ---------------------------------
__device__ float g_x[(size_t)N_TOTAL * D];
__device__ float g_y[(size_t)N_TOTAL * D];                 // -2 * out * sw
__device__ float g_a[N_TOTAL];
__device__ float g_scores[(size_t)N_TOTAL * N_TOTAL];      // 400 MB scratch
// pre-split tf32 operands (zero-padded rows up to NPAD)
__device__ unsigned g_yh[(size_t)NPAD * D];
__device__ unsigned g_yl[(size_t)NPAD * D];
__device__ unsigned g_oh[(size_t)NPAD * D];
__device__ unsigned g_ol[(size_t)NPAD * D];

// ---------------- f32x2 helpers (packed FFMA2) -----------------------------
__device__ __forceinline__ unsigned long long pack2(float x, float y) {
    unsigned long long r;
    asm("mov.b64 %0, {%1, %2};" : "=l"(r) : "f"(x), "f"(y));
    return r;
}
__device__ __forceinline__ float2 unpack2(unsigned long long v) {
    float x, y;
    asm("mov.b64 {%0, %1}, %2;" : "=f"(x), "=f"(y) : "l"(v));
    return make_float2(x, y);
}
__device__ __forceinline__ void fma2(unsigned long long& c,
                                     unsigned long long a,
                                     unsigned long long b) {
    asm("fma.rn.f32x2 %0, %1, %2, %3;" : "=l"(c) : "l"(a), "l"(b), "l"(c));
}

// ---------------- tf32 / mma helpers ----------------------------------------
__device__ __forceinline__ unsigned tf32_of(float x) {
    unsigned r;
    asm("cvt.rna.tf32.f32 %0, %1;" : "=r"(r) : "f"(x));
    return r;
}
__device__ __forceinline__ void mma_tf32(float* c, const unsigned* a,
                                         const unsigned* b) {
    asm volatile(
        "mma.sync.aligned.m16n8k8.row.col.f32.tf32.tf32.f32 "
        "{%0,%1,%2,%3}, {%4,%5,%6,%7}, {%8,%9}, {%0,%1,%2,%3};"
        : "+f"(c[0]), "+f"(c[1]), "+f"(c[2]), "+f"(c[3])
        : "r"(a[0]), "r"(a[1]), "r"(a[2]), "r"(a[3]), "r"(b[0]), "r"(b[1]));
}

// ===========================================================================
// Kernel 1: x = inputs @ W1^T + b1      (R9 proven fp32 version)
// ===========================================================================
__global__ void gemm1_kernel(const float* __restrict__ A,
                             const float* __restrict__ W,
                             const float* __restrict__ b1) {
    __shared__ __align__(16) float As[32][36];
    __shared__ __align__(16) float Bs[32][132];

    const int tid = threadIdx.x;
    const int mbase = blockIdx.x * 32;
    const int t = tid & 15;
    const int r0 = (tid >> 4) * 4;

    unsigned long long acc[4][4];
#pragma unroll
    for (int i = 0; i < 4; ++i)
#pragma unroll
        for (int u = 0; u < 4; ++u) acc[i][u] = 0ULL;

    const int lr = tid >> 3;
    const int lk = (tid & 7) * 4;

    for (int kc = 0; kc < FEAT; kc += 32) {
#pragma unroll
        for (int it = 0; it < 2; ++it) {
            int m = mbase + it * 16 + lr;
            float4 v = make_float4(0.f, 0.f, 0.f, 0.f);
            if (m < N_TOTAL)
                v = *(const float4*)&A[(size_t)m * FEAT + kc + lk];
            *(float4*)&As[it * 16 + lr][lk] = v;
        }
#pragma unroll
        for (int it = 0; it < 8; ++it) {
            int n = it * 16 + lr;
            float4 v = *(const float4*)&W[(size_t)n * FEAT + kc + lk];
            Bs[lk + 0][n] = v.x;
            Bs[lk + 1][n] = v.y;
            Bs[lk + 2][n] = v.z;
            Bs[lk + 3][n] = v.w;
        }
        __syncthreads();

#pragma unroll 8
        for (int kk = 0; kk < 32; ++kk) {
            unsigned long long bv[4];
#pragma unroll
            for (int u = 0; u < 4; ++u)
                bv[u] = *(const unsigned long long*)&Bs[kk][2 * t + 32 * u];
#pragma unroll
            for (int i = 0; i < 4; ++i) {
                float av = As[r0 + i][kk];
                unsigned long long ap = pack2(av, av);
#pragma unroll
                for (int u = 0; u < 4; ++u) fma2(acc[i][u], ap, bv[u]);
            }
        }
        __syncthreads();
    }

#pragma unroll
    for (int i = 0; i < 4; ++i) {
        int m = mbase + r0 + i;
        if (m < N_TOTAL) {
#pragma unroll
            for (int u = 0; u < 4; ++u) {
                int col = 2 * t + 32 * u;
                float2 c = unpack2(acc[i][u]);
                c.x += b1[col];
                c.y += b1[col + 1];
                *(float2*)&g_x[(size_t)m * D + col] = c;
            }
        }
    }
}

// ===========================================================================
// Kernel 2: BatchNorm per 100-row micro-batch + fused y/a
// ===========================================================================
__global__ void bn_kernel(const float* __restrict__ gamma,
                          const float* __restrict__ beta,
                          const float* __restrict__ sw,
                          float* __restrict__ outp) {
    const int b = blockIdx.x;
    const int c = threadIdx.x;
    __shared__ float arow[BSZ];
    if (c < BSZ) arow[c] = 0.f;

    const float* xb = g_x + (size_t)b * BSZ * D + c;
    float s = 0.f, s2 = 0.f;
    for (int r = 0; r < BSZ; ++r) {
        float v = xb[(size_t)r * D];
        s += v;
        s2 += v * v;
    }
    float mean = s * (1.f / BSZ);
    float var = s2 * (1.f / BSZ) - mean * mean;
    float rs = rsqrtf(var + 1e-5f);
    float g = gamma[c], be = beta[c], w = sw[c];
    __syncthreads();

    const int lane = c & 31;
    for (int r = 0; r < BSZ; ++r) {
        float v = xb[(size_t)r * D];
        float o = (v - mean) * rs * g + be;
        size_t idx = (size_t)(b * BSZ + r) * D + c;
        outp[idx] = o;
        g_y[idx] = -2.f * o * w;
        float contrib = w * o * o;
#pragma unroll
        for (int off = 16; off; off >>= 1)
            contrib += __shfl_down_sync(0xffffffffu, contrib, off);
        if (lane == 0) atomicAdd(&arow[r], contrib);
    }
    __syncthreads();
    if (c < BSZ) g_a[b * BSZ + c] = arow[c];
}

// ===========================================================================
// Prep: split g_y and outputs into tf32 hi/lo, rows >= N_TOTAL zeroed.
// (cvt.rna values bitwise-identical to R15's in-kernel splits.)
// ===========================================================================
__global__ void prep_yo_kernel(const float* __restrict__ O) {
    for (int i = blockIdx.x * blockDim.x + threadIdx.x; i < NPAD * D;
         i += gridDim.x * blockDim.x) {
        int row = i >> 7;
        float yv = 0.f, ov = 0.f;
        if (row < N_TOTAL) {
            yv = g_y[i];
            ov = O[i];
        }
        unsigned yh = tf32_of(yv);
        g_yh[i] = yh;
        g_yl[i] = tf32_of(yv - __uint_as_float(yh));
        unsigned oh = tf32_of(ov);
        g_oh[i] = oh;
        g_ol[i] = tf32_of(ov - __uint_as_float(oh));
    }
}

// ===========================================================================
// Kernel 3: scores via 3xTF32 mma.sync (R15 WIN structure); operand fill is
// a pure uint4 copy from pre-split global arrays (no CVT, no guards).
// ===========================================================================
__global__ void __launch_bounds__(256, 2)
scores_kernel(const float* __restrict__ sbp) {
    extern __shared__ __align__(16) unsigned smem_u[];
    unsigned (*Ah)[SLD] = (unsigned(*)[SLD])smem_u;
    unsigned (*Al)[SLD] = (unsigned(*)[SLD])(smem_u + 128 * SLD);
    unsigned (*Bh)[SLD] = (unsigned(*)[SLD])(smem_u + 2 * 128 * SLD);
    unsigned (*Bl)[SLD] = (unsigned(*)[SLD])(smem_u + 3 * 128 * SLD);

    int tt = blockIdx.x;
    int bi = 0;
    while (tt >= NTILES - bi) { tt -= NTILES - bi; ++bi; }
    const int bj = bi + tt;

    const int tid = threadIdx.x;
    const int lane = tid & 31;
    const int wid = tid >> 5;
    const int warp_m = wid & 1;
    const int warp_n = wid >> 1;
    const int g = lane >> 2;
    const int tig = lane & 3;

    const int ibase = bi * 128;
    const int jbase = bj * 128;

    float acc[4][4][4];
#pragma unroll
    for (int mt = 0; mt < 4; ++mt)
#pragma unroll
        for (int nt = 0; nt < 4; ++nt)
#pragma unroll
            for (int r = 0; r < 4; ++r) acc[mt][nt][r] = 0.f;

    const int frow = tid >> 1;
    const int fc0 = (tid & 1) * 16;

    for (int kc = 0; kc < D; kc += KC) {
        {
            const size_t abase = (size_t)(ibase + frow) * D + kc + fc0;
            const size_t bbase = (size_t)(jbase + frow) * D + kc + fc0;
#pragma unroll
            for (int q = 0; q < 4; ++q) {
                *(uint4*)&Ah[frow][fc0 + 4 * q] = *(const uint4*)&g_yh[abase + 4 * q];
                *(uint4*)&Al[frow][fc0 + 4 * q] = *(const uint4*)&g_yl[abase + 4 * q];
                *(uint4*)&Bh[frow][fc0 + 4 * q] = *(const uint4*)&g_oh[bbase + 4 * q];
                *(uint4*)&Bl[frow][fc0 + 4 * q] = *(const uint4*)&g_ol[bbase + 4 * q];
            }
        }
        __syncthreads();

#pragma unroll
        for (int ks = 0; ks < 4; ++ks) {
            const int k0 = ks * 8;
            unsigned bh[4][2], bl[4][2];
#pragma unroll
            for (int nt = 0; nt < 4; ++nt) {
                int n = warp_n * 32 + nt * 8 + g;
                bh[nt][0] = Bh[n][k0 + tig];
                bh[nt][1] = Bh[n][k0 + tig + 4];
                bl[nt][0] = Bl[n][k0 + tig];
                bl[nt][1] = Bl[n][k0 + tig + 4];
            }
#pragma unroll
            for (int mt = 0; mt < 4; ++mt) {
                int m = warp_m * 64 + mt * 16;
                unsigned ah[4], al[4];
                ah[0] = Ah[m + g][k0 + tig];
                ah[1] = Ah[m + g + 8][k0 + tig];
                ah[2] = Ah[m + g][k0 + tig + 4];
                ah[3] = Ah[m + g + 8][k0 + tig + 4];
                al[0] = Al[m + g][k0 + tig];
                al[1] = Al[m + g + 8][k0 + tig];
                al[2] = Al[m + g][k0 + tig + 4];
                al[3] = Al[m + g + 8][k0 + tig + 4];
#pragma unroll
                for (int nt = 0; nt < 4; ++nt) {
                    mma_tf32(acc[mt][nt], ah, bh[nt]);
                    mma_tf32(acc[mt][nt], ah, bl[nt]);
                    mma_tf32(acc[mt][nt], al, bh[nt]);
                }
            }
        }
        __syncthreads();
    }

    // ---- epilogue: relu(a_i + a_j + sb + dot), store + mirror ----
    const float sbv = *sbp;
    const bool full = (ibase + 128 <= N_TOTAL) && (jbase + 128 <= N_TOTAL);

#pragma unroll
    for (int mt = 0; mt < 4; ++mt) {
        int gi0 = ibase + warp_m * 64 + mt * 16 + g;
        int gi1 = gi0 + 8;
        float ai0 = (gi0 < N_TOTAL) ? g_a[gi0] : 0.f;
        float ai1 = (gi1 < N_TOTAL) ? g_a[gi1] : 0.f;
#pragma unroll
        for (int nt = 0; nt < 4; ++nt) {
            int gj = jbase + warp_n * 32 + nt * 8 + 2 * tig;
            float aj0 = (gj < N_TOTAL) ? g_a[gj] : 0.f;
            float aj1 = (gj + 1 < N_TOTAL) ? g_a[gj + 1] : 0.f;
            const float* c = acc[mt][nt];
            float s00 = fmaxf(ai0 + aj0 + sbv + c[0], 0.f);
            float s01 = fmaxf(ai0 + aj1 + sbv + c[1], 0.f);
            float s10 = fmaxf(ai1 + aj0 + sbv + c[2], 0.f);
            float s11 = fmaxf(ai1 + aj1 + sbv + c[3], 0.f);
            if (full) {
                *(float2*)&g_scores[(size_t)gi0 * N_TOTAL + gj] =
                    make_float2(s00, s01);
                *(float2*)&g_scores[(size_t)gi1 * N_TOTAL + gj] =
                    make_float2(s10, s11);
                if (bi != bj) {
                    g_scores[(size_t)gj * N_TOTAL + gi0] = s00;
                    g_scores[(size_t)gj * N_TOTAL + gi1] = s10;
                    g_scores[(size_t)(gj + 1) * N_TOTAL + gi0] = s01;
                    g_scores[(size_t)(gj + 1) * N_TOTAL + gi1] = s11;
                }
            } else {
                if (gi0 < N_TOTAL && gj < N_TOTAL)
                    g_scores[(size_t)gi0 * N_TOTAL + gj] = s00;
                if (gi0 < N_TOTAL && gj + 1 < N_TOTAL)
                    g_scores[(size_t)gi0 * N_TOTAL + gj + 1] = s01;
                if (gi1 < N_TOTAL && gj < N_TOTAL)
                    g_scores[(size_t)gi1 * N_TOTAL + gj] = s10;
                if (gi1 < N_TOTAL && gj + 1 < N_TOTAL)
                    g_scores[(size_t)gi1 * N_TOTAL + gj + 1] = s11;
                if (bi != bj) {
                    if (gj < N_TOTAL && gi0 < N_TOTAL)
                        g_scores[(size_t)gj * N_TOTAL + gi0] = s00;
                    if (gj < N_TOTAL && gi1 < N_TOTAL)
                        g_scores[(size_t)gj * N_TOTAL + gi1] = s10;
                    if (gj + 1 < N_TOTAL && gi0 < N_TOTAL)
                        g_scores[(size_t)(gj + 1) * N_TOTAL + gi0] = s01;
                    if (gj + 1 < N_TOTAL && gi1 < N_TOTAL)
                        g_scores[(size_t)(gj + 1) * N_TOTAL + gi1] = s11;
                }
            }
        }
    }
}

// ===========================================================================
// Kernel 4: per-row exact top-50 — single-pass threshold buffer (R6 proven).
// ===========================================================================
__global__ void __launch_bounds__(256) topk_kernel(float* __restrict__ S) {
    __shared__ float bval[CAP];
    __shared__ int   bidx[CAP];
    __shared__ unsigned hist[256];
    __shared__ int idxbuf[64];
    __shared__ int eqbuf[256];
    __shared__ float vbuf[TOPK];
    __shared__ float ebuf[TOPK];
    __shared__ int bcount, cnt_gt, cnt_eq;
    __shared__ unsigned sh_sel;
    __shared__ int sh_krem, sh_binc;
    __shared__ unsigned sh_thr;
    __shared__ float sh_inv;

    const int row = blockIdx.x;
    const int tid = threadIdx.x;
    const int lane = tid & 31;

    const float* rowp = g_scores + (size_t)row * N_TOTAL;
    const float4* rp4 = (const float4*)rowp;
    float4* sp4 = (float4*)(S + (size_t)row * N_TOTAL);

    if (tid == 0) { bcount = 0; cnt_gt = 0; cnt_eq = 0; sh_thr = 0; }
    __syncthreads();

#define WARP_SELECT(ARR, KREM)                                                \
    if (tid < 32) {                                                           \
        unsigned h[8], ls[8];                                                 \
        int b0 = lane * 8;                                                    \
        _Pragma("unroll")                                                     \
        for (int j = 0; j < 8; ++j) h[j] = (ARR)[b0 + j];                     \
        ls[7] = h[7];                                                         \
        _Pragma("unroll")                                                     \
        for (int j = 6; j >= 0; --j) ls[j] = ls[j + 1] + h[j];                \
        unsigned tot = ls[0];                                                 \
        unsigned ss = tot;                                                    \
        _Pragma("unroll")                                                     \
        for (int off = 1; off < 32; off <<= 1) {                              \
            unsigned o = __shfl_down_sync(0xffffffffu, ss, off);              \
            if (lane + off < 32) ss += o;                                     \
        }                                                                     \
        unsigned above = ss - tot;                                            \
        int best = -1;                                                        \
        _Pragma("unroll")                                                     \
        for (int j = 7; j >= 0; --j)                                          \
            if (best < 0 && above + ls[j] >= (unsigned)(KREM)) best = j;      \
        unsigned m = __ballot_sync(0xffffffffu, best >= 0);                   \
        int hi = 31 - __clz((int)m);                                          \
        if (lane == hi) {                                                     \
            unsigned Sb = above + ls[best];                                   \
            sh_sel = (unsigned)(b0 + best);                                   \
            sh_binc = (int)h[best];                                           \
            sh_krem = (KREM) - (int)(Sb - h[best]);                           \
        }                                                                     \
    }

#define EXACT_SELECT(CNT, KINIT, PREFIX, KREM)                                \
    {                                                                         \
        (PREFIX) = 0; (KREM) = (KINIT);                                       \
        const int SHS[4] = {24, 16, 8, 0};                                    \
        const unsigned HMS[4] = {0u, 0xFF000000u, 0xFFFF0000u, 0xFFFFFF00u};  \
        for (int ps = 0; ps < 4; ++ps) {                                      \
            hist[tid] = 0;                                                    \
            __syncthreads();                                                  \
            for (int i = tid; i < (CNT); i += 256) {                          \
                unsigned b = __float_as_uint(bval[i]);                        \
                if ((b & HMS[ps]) == ((PREFIX) & HMS[ps]))                    \
                    atomicAdd(&hist[(b >> SHS[ps]) & 255u], 1u);              \
            }                                                                 \
            __syncthreads();                                                  \
            WARP_SELECT(hist, (KREM))                                         \
            __syncthreads();                                                  \
            (PREFIX) |= sh_sel << SHS[ps];                                    \
            (KREM) = sh_krem;                                                 \
            __syncthreads();                                                  \
        }                                                                     \
    }

#define PUSH(V, IDX)                                                          \
    {                                                                         \
        unsigned b_ = __float_as_uint(V);                                     \
        if (b_ >= thr) {                                                      \
            unsigned mk = __activemask();                                     \
            int ldr = __ffs(mk) - 1;                                          \
            int rk = __popc(mk & ((1u << lane) - 1));                         \
            int bs;                                                           \
            if (lane == ldr) bs = atomicAdd(&bcount, __popc(mk));             \
            bs = __shfl_sync(mk, bs, ldr);                                    \
            int p_ = bs + rk;                                                 \
            if (p_ < CAP) { bval[p_] = (V); bidx[p_] = (IDX); }               \
        }                                                                     \
    }

    unsigned thr = 0;
    const float4 z = make_float4(0.f, 0.f, 0.f, 0.f);

    for (int chunk = 0; chunk < 10; ++chunk) {
        if (bcount > CAP - 1024) {
            unsigned pfx; int kr;
            EXACT_SELECT(bcount, TOPK, pfx, kr)
            (void)kr;
            const int cnt = bcount;
            float mv[8]; int mi[8]; int mc = 0;
            for (int i = tid; i < cnt; i += 256) {
                unsigned b = __float_as_uint(bval[i]);
                if (b >= pfx) { mv[mc] = bval[i]; mi[mc] = bidx[i]; ++mc; }
            }
            __syncthreads();
            if (tid == 0) { bcount = 0; sh_thr = pfx; }
            __syncthreads();
            for (int j = 0; j < mc; ++j) {
                int p = atomicAdd(&bcount, 1);
                bval[p] = mv[j]; bidx[p] = mi[j];
            }
            __syncthreads();
            thr = sh_thr;
        }

        int i4 = chunk * 256 + tid;
        if (i4 < NF4) {
            float4 val = rp4[i4];
            sp4[i4] = z;
            PUSH(val.x, 4 * i4 + 0)
            PUSH(val.y, 4 * i4 + 1)
            PUSH(val.z, 4 * i4 + 2)
            PUSH(val.w, 4 * i4 + 3)
        }
        __syncthreads();
    }

    const int nc = bcount;
    unsigned prefix; int krem;
    EXACT_SELECT(nc, TOPK, prefix, krem)

    for (int i = tid; i < nc; i += 256) {
        unsigned b = __float_as_uint(bval[i]);
        if (b > prefix) {
            int p = atomicAdd(&cnt_gt, 1);
            idxbuf[p] = bidx[i];
        } else if (b == prefix) {
            int p = atomicAdd(&cnt_eq, 1);
            if (p < 256) eqbuf[p] = bidx[i];
        }
    }
    __syncthreads();

    if (tid == 0) {
        int n = cnt_gt;
        int need = TOPK - n;
        if (cnt_eq <= 256) {
            for (int t2 = 0; t2 < need; ++t2) {
                int best = 0x7fffffff, bj2 = 0;
                for (int j2 = 0; j2 < cnt_eq; ++j2) {
                    int vv = eqbuf[j2];
                    if (vv < best) { best = vv; bj2 = j2; }
                }
                idxbuf[n++] = best;
                eqbuf[bj2] = 0x7fffffff;
            }
        } else {
            for (int t2 = 0; t2 < need; ++t2) {
                int best = 0x7fffffff, bj2 = -1;
                for (int i = 0; i < nc; ++i) {
                    if (__float_as_uint(bval[i]) == prefix && bidx[i] < best) {
                        best = bidx[i]; bj2 = i;
                    }
                }
                idxbuf[n++] = best;
                if (bj2 >= 0) bidx[bj2] = 0x7fffffff;
            }
        }
    }
    __syncthreads();

    if (tid < TOPK) vbuf[tid] = rowp[idxbuf[tid]];
    __syncthreads();
    if (tid == 0) {
        float mx = -1e30f;
        for (int t2 = 0; t2 < TOPK; ++t2) mx = fmaxf(mx, vbuf[t2]);
        float ssum = 0.f;
        for (int t2 = 0; t2 < TOPK; ++t2) {
            float e = expf(vbuf[t2] - mx);
            ebuf[t2] = e;
            ssum += e;
        }
        sh_inv = 1.f / ssum;
    }
    __syncthreads();
    if (tid < TOPK)
        S[(size_t)row * N_TOTAL + idxbuf[tid]] = ebuf[tid] * sh_inv;

#undef PUSH
#undef EXACT_SELECT
#undef WARP_SELECT
}

// ===========================================================================
extern "C" void kernel_launch(void* const* d_in, const int* in_sizes, int n_in,
                              void* d_out, int out_size) {
    const float* inputs = (const float*)d_in[0];
    const float* W1     = (const float*)d_in[1];
    const float* b1     = (const float*)d_in[2];
    const float* gamma  = (const float*)d_in[3];
    const float* beta   = (const float*)d_in[4];
    const float* sw     = (const float*)d_in[5];
    const float* sb     = (const float*)d_in[6];

    float* outp = (float*)d_out;                       // [10000,128] outputs
    float* Sp   = outp + (size_t)N_TOTAL * D;          // [10000,10000] S

    cudaFuncSetAttribute(scores_kernel,
                         cudaFuncAttributeMaxDynamicSharedMemorySize, SC_SMEM);

    gemm1_kernel<<<(N_TOTAL + 31) / 32, 128>>>(inputs, W1, b1);
    bn_kernel<<<N_TOTAL / BSZ, D>>>(gamma, beta, sw, outp);
    prep_yo_kernel<<<640, 256>>>(outp);
    scores_kernel<<<TRI_BLOCKS, 256, SC_SMEM>>>(sb);
    topk_kernel<<<N_TOTAL, 256>>>(Sp);
}